// round 15
// baseline (speedup 1.0000x reference)
#include <cuda_runtime.h>
#include <cuda_bf16.h>
#include <cuda_fp16.h>
#include <cstdint>

#define N_NODES 100000
#define N_EDGES 3200000
#define K1 512      // in_dim * n_seq
#define H1 256
#define H2 128
#define ENDD 64

// ---------------- scratch (device globals; no allocation allowed) -----------
__device__ __half g_Hh[(size_t)N_NODES * H1];  // GEMM outputs, fp16 (agg input)
__device__ __half g_Xh[(size_t)N_NODES * H1];  // layer-2 GEMM input (agg1 out)
__device__ int   g_deg_out[N_NODES];
__device__ int   g_deg_in[N_NODES];
__device__ float g_sout[N_NODES];
__device__ float g_sin[N_NODES];
__device__ int   g_rowptr[N_NODES + 1];
__device__ int   g_cursor[N_NODES];
__device__ int   g_colsrc[N_EDGES];
#define SCAN_BLOCKS ((N_NODES + 1023) / 1024)   // 98
__device__ int   g_part[128];
__device__ int   g_poff[128];
// transposed fp16 weights: Wt[n][k]
__device__ __half g_W1t[H1 * K1];
__device__ __half g_W2t[H2 * H1];
__device__ __half g_Wo1t[ENDD * H2];

// ---------------- PTX helpers ------------------------------------------------
__device__ __forceinline__ uint32_t smem_u32(const void* p) {
    uint32_t a;
    asm("{ .reg .u64 t; cvta.to.shared.u64 t, %1; cvt.u32.u64 %0, t; }"
        : "=r"(a) : "l"(p));
    return a;
}

__device__ __forceinline__ void ldsm_x4(uint32_t (&r)[4], uint32_t a) {
    asm volatile("ldmatrix.sync.aligned.m8n8.x4.shared.b16 {%0,%1,%2,%3}, [%4];"
                 : "=r"(r[0]), "=r"(r[1]), "=r"(r[2]), "=r"(r[3]) : "r"(a));
}

__device__ __forceinline__ void ldsm_x2(uint32_t (&r)[2], uint32_t a) {
    asm volatile("ldmatrix.sync.aligned.m8n8.x2.shared.b16 {%0,%1}, [%2];"
                 : "=r"(r[0]), "=r"(r[1]) : "r"(a));
}

__device__ __forceinline__ void mma_fp16(float (&d)[4], const uint32_t (&a)[4],
                                         const uint32_t (&b)[2]) {
    asm volatile(
        "mma.sync.aligned.m16n8k16.row.col.f32.f16.f16.f32 "
        "{%0,%1,%2,%3}, {%4,%5,%6,%7}, {%8,%9}, {%0,%1,%2,%3};"
        : "+f"(d[0]), "+f"(d[1]), "+f"(d[2]), "+f"(d[3])
        : "r"(a[0]), "r"(a[1]), "r"(a[2]), "r"(a[3]), "r"(b[0]), "r"(b[1]));
}

__device__ __forceinline__ void cp_async16(uint32_t smem_dst, const void* gsrc,
                                           int src_bytes) {
    asm volatile("cp.async.cg.shared.global [%0], [%1], 16, %2;"
                 :: "r"(smem_dst), "l"(gsrc), "r"(src_bytes));
}
__device__ __forceinline__ void cp_commit() {
    asm volatile("cp.async.commit_group;");
}
__device__ __forceinline__ void cp_wait_all() {
    asm volatile("cp.async.wait_group 0;");
}

// ---------------- graph preprocessing ---------------------------------------
__global__ void zero_deg_kernel() {
    int i = blockIdx.x * blockDim.x + threadIdx.x;
    if (i < N_NODES) { g_deg_out[i] = 0; g_deg_in[i] = 0; }
}

// split degree kernels (N_EDGES divisible by 4)
__global__ void degree_out_kernel(const int4* __restrict__ src4) {
    for (int i = blockIdx.x * blockDim.x + threadIdx.x; i < N_EDGES / 4;
         i += gridDim.x * blockDim.x) {
        int4 s = src4[i];
        atomicAdd(&g_deg_out[s.x], 1); atomicAdd(&g_deg_out[s.y], 1);
        atomicAdd(&g_deg_out[s.z], 1); atomicAdd(&g_deg_out[s.w], 1);
    }
}

__global__ void degree_in_kernel(const int4* __restrict__ dst4) {
    for (int i = blockIdx.x * blockDim.x + threadIdx.x; i < N_EDGES / 4;
         i += gridDim.x * blockDim.x) {
        int4 d = dst4[i];
        atomicAdd(&g_deg_in[d.x], 1); atomicAdd(&g_deg_in[d.y], 1);
        atomicAdd(&g_deg_in[d.z], 1); atomicAdd(&g_deg_in[d.w], 1);
    }
}

__global__ void scales_out_kernel() {
    int i = blockIdx.x * blockDim.x + threadIdx.x;
    if (i < N_NODES) g_sout[i] = rsqrtf((float)max(g_deg_out[i], 1));
}

__global__ void scales_in_kernel() {
    int i = blockIdx.x * blockDim.x + threadIdx.x;
    if (i < N_NODES) g_sin[i] = rsqrtf((float)max(g_deg_in[i], 1));
}

__global__ void scan_block_kernel() {
    __shared__ int sh[1024];
    int t = threadIdx.x;
    int i = blockIdx.x * 1024 + t;
    int v = (i < N_NODES) ? g_deg_in[i] : 0;
    sh[t] = v;
    __syncthreads();
    for (int off = 1; off < 1024; off <<= 1) {
        int x = sh[t];
        int y = (t >= off) ? sh[t - off] : 0;
        __syncthreads();
        sh[t] = x + y;
        __syncthreads();
    }
    if (i < N_NODES) g_rowptr[i] = sh[t] - v;
    if (t == 1023) g_part[blockIdx.x] = sh[1023];
}

__global__ void scan_part_kernel() {
    __shared__ int sh[128];
    int t = threadIdx.x;
    int v = (t < SCAN_BLOCKS) ? g_part[t] : 0;
    sh[t] = v;
    __syncthreads();
    for (int off = 1; off < 128; off <<= 1) {
        int x = sh[t];
        int y = (t >= off) ? sh[t - off] : 0;
        __syncthreads();
        sh[t] = x + y;
        __syncthreads();
    }
    g_poff[t] = sh[t] - v;
}

__global__ void scan_finish_kernel() {
    int i = blockIdx.x * blockDim.x + threadIdx.x;
    if (i < N_NODES) {
        int r = g_rowptr[i] + g_poff[i >> 10];
        g_rowptr[i] = r;
        g_cursor[i] = r;
    }
    if (i == 0) g_rowptr[N_NODES] = N_EDGES;
}

__global__ void csr_fill_kernel(const int4* __restrict__ src4,
                                const int4* __restrict__ dst4) {
    for (int i = blockIdx.x * blockDim.x + threadIdx.x; i < N_EDGES / 4;
         i += gridDim.x * blockDim.x) {
        int4 d = dst4[i];
        int4 s = src4[i];
        g_colsrc[atomicAdd(&g_cursor[d.x], 1)] = s.x;
        g_colsrc[atomicAdd(&g_cursor[d.y], 1)] = s.y;
        g_colsrc[atomicAdd(&g_cursor[d.z], 1)] = s.z;
        g_colsrc[atomicAdd(&g_cursor[d.w], 1)] = s.w;
    }
}

// ------- weight transpose to fp16: W[K][N] -> Wt[N][K] ----------------------
__global__ void wconv_kernel(const float* __restrict__ W, __half* __restrict__ T,
                             int K, int N) {
    int i = blockIdx.x * blockDim.x + threadIdx.x;
    if (i < K * N) {
        int k = i / N, n = i % N;
        T[(size_t)n * K + k] = __float2half_rn(W[i]);
    }
}

#define GPAD 40   // fp16 elements per SMEM row (80 B): conflict-free ldmatrix

// ---------------- GEMM1: fp32 A (feat), BM=64 x BN=256(all of N), BK=32 ------
// Epilogue multiplies row r by g_sout[r] (fp32, exact).
#define G1_AH_OFF   0u          // 64 x GPAD fp16 = 5120 (single)
#define G1_RAWA_OFF 5120u       // 2 x 8192 (64x32 fp32)
#define G1_RAWA_STR 8192u
#define G1_BH_OFF   21504u      // 2 x 20480 (256 x GPAD fp16)
#define G1_BSTAGE   20480u
#define G1_SMEM     62464

__global__ __launch_bounds__(256, 2)
void gemm1_wide(const float* __restrict__ A, const __half* __restrict__ Bh, int M) {
    extern __shared__ __align__(16) char smem[];
    const uint32_t sm = smem_u32(smem);

    const int tid = threadIdx.x;
    const int lane = tid & 31, warp = tid >> 5;
    const int wm = warp >> 2, wn = warp & 3;     // 2 x 4 warp grid
    const int bm = blockIdx.x;

    float c[2][8][4];
#pragma unroll
    for (int mi = 0; mi < 2; mi++)
#pragma unroll
        for (int ni = 0; ni < 8; ni++)
#pragma unroll
            for (int q = 0; q < 4; q++) c[mi][ni][q] = 0.f;

    const int kiters = K1 / 32;    // 16

    auto issue_stage = [&](int kt, int stage) {
        const int k0 = kt * 32;
        const uint32_t rawA = sm + G1_RAWA_OFF + (uint32_t)stage * G1_RAWA_STR;
#pragma unroll
        for (int j = 0; j < 2; j++) {
            const int cchunk = j * 256 + tid;             // 0..511
            const int row = cchunk >> 3, cc = (cchunk & 7) * 4;
            const int grow = bm * 64 + row;
            cp_async16(rawA + (uint32_t)(row * 128 + cc * 4),
                       A + (size_t)grow * K1 + k0 + cc, (grow < M) ? 16 : 0);
        }
        const uint32_t bh = sm + G1_BH_OFF + (uint32_t)stage * G1_BSTAGE;
#pragma unroll
        for (int j = 0; j < 4; j++) {
            const int cchunk = j * 256 + tid;             // 0..1023
            const int row = cchunk >> 2, cc = (cchunk & 3) * 8;   // row 0..255
            cp_async16(bh + (uint32_t)(row * (GPAD * 2) + cc * 2),
                       Bh + (size_t)row * K1 + k0 + cc, 16);
        }
        cp_commit();
    };

    issue_stage(0, 0);

    for (int kt = 0; kt < kiters; kt++) {
        const int stage = kt & 1;
        cp_wait_all();
        __syncthreads();

        if (kt + 1 < kiters) issue_stage(kt + 1, stage ^ 1);

        // convert rawA[stage] fp32 -> fp16 into single Ah buffer
        {
            const float4* raw =
                (const float4*)(smem + G1_RAWA_OFF + (uint32_t)stage * G1_RAWA_STR);
            __half* AhP = (__half*)(smem + G1_AH_OFF);
#pragma unroll
            for (int j = 0; j < 2; j++) {
                const int cchunk = j * 256 + tid;
                const int row = cchunk >> 3, col = (cchunk & 7) * 4;
                float4 v = raw[row * 8 + (cchunk & 7)];
                const int off = row * GPAD + col;
                *(__half2*)&AhP[off]     = __floats2half2_rn(v.x, v.y);
                *(__half2*)&AhP[off + 2] = __floats2half2_rn(v.z, v.w);
            }
        }
        __syncthreads();

        const uint32_t sAh = sm + G1_AH_OFF;
        const uint32_t sBh = sm + G1_BH_OFF + (uint32_t)stage * G1_BSTAGE;
#pragma unroll
        for (int kk = 0; kk < 2; kk++) {
            const int kc = kk * 16;
            const int l16 = lane & 15;
            uint32_t bhf[8][2];
#pragma unroll
            for (int ni = 0; ni < 8; ni++) {
                const uint32_t boff =
                    (uint32_t)((wn * 64 + ni * 8 + (l16 & 7)) * GPAD + kc + (l16 >> 3) * 8) * 2u;
                ldsm_x2(bhf[ni], sBh + boff);
            }
#pragma unroll
            for (int mi = 0; mi < 2; mi++) {
                const uint32_t aoff =
                    (uint32_t)((wm * 32 + mi * 16 + (lane & 15)) * GPAD + kc + (lane >> 4) * 8) * 2u;
                uint32_t ahf[4];
                ldsm_x4(ahf, sAh + aoff);
#pragma unroll
                for (int ni = 0; ni < 8; ni++)
                    mma_fp16(c[mi][ni], ahf, bhf[ni]);
            }
        }
    }

    // epilogue: row-scale by sout, then fp16 store
#pragma unroll
    for (int mi = 0; mi < 2; mi++) {
        const int r0 = bm * 64 + wm * 32 + mi * 16 + (lane >> 2);
        const float s0 = (r0 < M) ? g_sout[r0] : 0.f;
        const float s1 = (r0 + 8 < M) ? g_sout[r0 + 8] : 0.f;
#pragma unroll
        for (int ni = 0; ni < 8; ni++) {
            const int col = wn * 64 + ni * 8 + 2 * (lane & 3);
            if (r0 < M)
                *(__half2*)(g_Hh + (size_t)r0 * H1 + col) =
                    __floats2half2_rn(c[mi][ni][0] * s0, c[mi][ni][1] * s0);
            if (r0 + 8 < M)
                *(__half2*)(g_Hh + (size_t)(r0 + 8) * H1 + col) =
                    __floats2half2_rn(c[mi][ni][2] * s1, c[mi][ni][3] * s1);
        }
    }
}

// ---------------- GEMM2: fp16 A (g_Xh), BM=128 x BN=128, BK=32 ---------------
#define G2_AH_OFF  0u           // 2 x 10240
#define G2_AH_STR  10240u
#define G2_BH_OFF  20480u       // 2 x 10240
#define G2_BSTAGE  10240u
#define G2_SMEM    40960

__global__ __launch_bounds__(256, 2)
void gemm2_fp16(const __half* __restrict__ Bh, int M) {
    extern __shared__ __align__(16) char smem[];
    const uint32_t sm = smem_u32(smem);

    const int tid = threadIdx.x;
    const int lane = tid & 31, warp = tid >> 5;
    const int wm = warp >> 2, wn = warp & 3;
    const int bm = blockIdx.x;

    float c[4][4][4];
#pragma unroll
    for (int mi = 0; mi < 4; mi++)
#pragma unroll
        for (int ni = 0; ni < 4; ni++)
#pragma unroll
            for (int q = 0; q < 4; q++) c[mi][ni][q] = 0.f;

    const int kiters = H1 / 32;   // 8

    auto issue_stage = [&](int kt, int stage) {
        const int k0 = kt * 32;
        const uint32_t ah = sm + G2_AH_OFF + (uint32_t)stage * G2_AH_STR;
#pragma unroll
        for (int j = 0; j < 2; j++) {
            const int cchunk = j * 256 + tid;         // 0..511
            const int row = cchunk >> 2, cc = cchunk & 3;
            const int grow = bm * 128 + row;
            cp_async16(ah + (uint32_t)(row * (GPAD * 2) + cc * 16),
                       g_Xh + (size_t)grow * H1 + k0 + cc * 8,
                       (grow < M) ? 16 : 0);
        }
        const uint32_t bh = sm + G2_BH_OFF + (uint32_t)stage * G2_BSTAGE;
#pragma unroll
        for (int j = 0; j < 2; j++) {
            const int cchunk = j * 256 + tid;
            const int row = cchunk >> 2, cc = (cchunk & 3) * 8;
            cp_async16(bh + (uint32_t)(row * (GPAD * 2) + cc * 2),
                       Bh + (size_t)row * H1 + k0 + cc, 16);
        }
        cp_commit();
    };

    issue_stage(0, 0);

    for (int kt = 0; kt < kiters; kt++) {
        const int stage = kt & 1;
        cp_wait_all();
        __syncthreads();

        if (kt + 1 < kiters) issue_stage(kt + 1, stage ^ 1);

        const uint32_t sAh = sm + G2_AH_OFF + (uint32_t)stage * G2_AH_STR;
        const uint32_t sBh = sm + G2_BH_OFF + (uint32_t)stage * G2_BSTAGE;
#pragma unroll
        for (int kk = 0; kk < 2; kk++) {
            const int kc = kk * 16;
            const int l16 = lane & 15;
            uint32_t bhf[4][2];
#pragma unroll
            for (int ni = 0; ni < 4; ni++) {
                const uint32_t boff =
                    (uint32_t)((wn * 32 + ni * 8 + (l16 & 7)) * GPAD + kc + (l16 >> 3) * 8) * 2u;
                ldsm_x2(bhf[ni], sBh + boff);
            }
#pragma unroll
            for (int mi = 0; mi < 4; mi++) {
                const uint32_t aoff =
                    (uint32_t)((wm * 64 + mi * 16 + (lane & 15)) * GPAD + kc + (lane >> 4) * 8) * 2u;
                uint32_t ahf[4];
                ldsm_x4(ahf, sAh + aoff);
#pragma unroll
                for (int ni = 0; ni < 4; ni++)
                    mma_fp16(c[mi][ni], ahf, bhf[ni]);
            }
        }
    }

#pragma unroll
    for (int mi = 0; mi < 4; mi++) {
        const int r0 = bm * 128 + wm * 64 + mi * 16 + (lane >> 2);
#pragma unroll
        for (int ni = 0; ni < 4; ni++) {
            const int col = wn * 32 + ni * 8 + 2 * (lane & 3);
            if (r0 < M)
                *(__half2*)(g_Hh + (size_t)r0 * H2 + col) =
                    __floats2half2_rn(c[mi][ni][0], c[mi][ni][1]);
            if (r0 + 8 < M)
                *(__half2*)(g_Hh + (size_t)(r0 + 8) * H2 + col) =
                    __floats2half2_rn(c[mi][ni][2], c[mi][ni][3]);
        }
    }
}

// ---------------- warp-per-node aggregation, layer 1 (fp16 gather) -----------
// One warp per node; shfl-distributed index prefetch; one LDG.128 per edge.
__global__ __launch_bounds__(256)
void aggregate_warp1(const float* __restrict__ bias) {
    const int warp = threadIdx.x >> 5, lane = threadIdx.x & 31;
    const int v = blockIdx.x * 8 + warp;
    if (v >= N_NODES) return;
    constexpr int EPT = H1 / 32;          // 8

    float acc[EPT];
#pragma unroll
    for (int i = 0; i < EPT; i++) acc[i] = 0.f;

    const __half* __restrict__ Hm = g_Hh;

    auto add_row = [&](int s) {
        const __half* r = Hm + (size_t)s * H1 + lane * EPT;
        const uint4 d = *(const uint4*)r;
        const float2 f0 = __half22float2(*(const __half2*)&d.x);
        const float2 f1 = __half22float2(*(const __half2*)&d.y);
        const float2 f2 = __half22float2(*(const __half2*)&d.z);
        const float2 f3 = __half22float2(*(const __half2*)&d.w);
        acc[0] += f0.x; acc[1] += f0.y; acc[2] += f1.x; acc[3] += f1.y;
        acc[4] += f2.x; acc[5] += f2.y; acc[6] += f3.x; acc[7] += f3.y;
    };

    const int beg = g_rowptr[v];
    const int end = g_rowptr[v + 1];
    for (int base = beg; base < end; base += 32) {
        const int cnt = min(32, end - base);
        int idx = 0;
        if (lane < cnt) idx = g_colsrc[base + lane];
        int j = 0;
        for (; j + 4 <= cnt; j += 4) {
            const int s0 = __shfl_sync(0xffffffffu, idx, j);
            const int s1 = __shfl_sync(0xffffffffu, idx, j + 1);
            const int s2 = __shfl_sync(0xffffffffu, idx, j + 2);
            const int s3 = __shfl_sync(0xffffffffu, idx, j + 3);
            add_row(s0); add_row(s1); add_row(s2); add_row(s3);
        }
        for (; j < cnt; j++) add_row(__shfl_sync(0xffffffffu, idx, j));
    }

    const float si = g_sin[v];
    const float so = g_sout[v];
    float o[EPT];
#pragma unroll
    for (int i = 0; i < EPT; i += 4) {
        const float4 b = *(const float4*)(bias + lane * EPT + i);
        o[i]     = fmaxf(fmaf(acc[i],     si, b.x), 0.f) * so;
        o[i + 1] = fmaxf(fmaf(acc[i + 1], si, b.y), 0.f) * so;
        o[i + 2] = fmaxf(fmaf(acc[i + 2], si, b.z), 0.f) * so;
        o[i + 3] = fmaxf(fmaf(acc[i + 3], si, b.w), 0.f) * so;
    }
    __half2 h[EPT / 2];
#pragma unroll
    for (int i = 0; i < EPT / 2; i++) h[i] = __floats2half2_rn(o[2 * i], o[2 * i + 1]);
    *(uint4*)(g_Xh + (size_t)v * H1 + lane * EPT) = *(uint4*)h;
}

// ------- fused head: agg2 (gather from g_Hh) + relu(X2@Wo1+bo1)@Wo2+bo2 -----
// Phase 1: 8 warps aggregate 16 nodes each (EPT=4, uint2 per edge), writing
// fp16 X2 rows directly into MMA-ready SMEM A (4 k-chunks, GPAD layout).
// Phase 2: 4 k-iter MMA from SMEM; fused relu+Wo2 epilogue.
#define HF_A_OFF   0u           // 4 x 10240 = 40960
#define HF_ACH     10240u
#define HF_B_OFF   40960u       // 4 x 5120 = 20480
#define HF_BCH     5120u
#define HF_RED_OFF 61440u       // 128 x 4 floats
#define HF_SMEM    63488

__global__ __launch_bounds__(256, 2)
void head_fused(const __half* __restrict__ Bh, const float* __restrict__ b2,
                const float* __restrict__ bo1, const float* __restrict__ Wo2,
                const float* __restrict__ bo2, float* __restrict__ out, int M) {
    extern __shared__ __align__(16) char smem[];
    const uint32_t sm = smem_u32(smem);

    const int tid = threadIdx.x;
    const int lane = tid & 31, warp = tid >> 5;
    const int wm = warp >> 2, wn = warp & 3;
    const int bm = blockIdx.x;

    // ---- issue all of B (Wo1t, 64x128) via cp.async ----
#pragma unroll
    for (int j = 0; j < 4; j++) {
        const int i = j * 256 + tid;          // 0..1023
        const int row = i >> 4, c16 = i & 15; // row 0..63; 16B chunk in row
        const int kch = c16 >> 2, cc = (c16 & 3) * 8;
        cp_async16(sm + HF_B_OFF + (uint32_t)(kch * HF_BCH + row * (GPAD * 2) + cc * 2),
                   Bh + (size_t)row * H2 + kch * 32 + cc, 16);
    }
    cp_commit();

    // ---- phase 1: aggregate 16 nodes per warp into SMEM A ----
    {
        constexpr int EPT = H2 / 32;          // 4
        const int kch = lane >> 3, cc = (lane & 7) * 4;   // this lane's cols
        const float4 bvec_ok = *(const float4*)(b2 + lane * EPT);
        const __half* __restrict__ Hm = g_Hh;

        for (int i = 0; i < 16; i++) {
            const int r = warp * 16 + i;       // local row 0..127
            const int v = bm * 128 + r;
            float acc0 = 0.f, acc1 = 0.f, acc2 = 0.f, acc3 = 0.f;
            if (v < M) {
                const int beg = g_rowptr[v];
                const int end = g_rowptr[v + 1];
                auto add_row = [&](int s) {
                    const uint2 d = *(const uint2*)(Hm + (size_t)s * H2 + lane * EPT);
                    const float2 f0 = __half22float2(*(const __half2*)&d.x);
                    const float2 f1 = __half22float2(*(const __half2*)&d.y);
                    acc0 += f0.x; acc1 += f0.y; acc2 += f1.x; acc3 += f1.y;
                };
                for (int base = beg; base < end; base += 32) {
                    const int cnt = min(32, end - base);
                    int idx = 0;
                    if (lane < cnt) idx = g_colsrc[base + lane];
                    int j = 0;
                    for (; j + 4 <= cnt; j += 4) {
                        const int s0 = __shfl_sync(0xffffffffu, idx, j);
                        const int s1 = __shfl_sync(0xffffffffu, idx, j + 1);
                        const int s2 = __shfl_sync(0xffffffffu, idx, j + 2);
                        const int s3 = __shfl_sync(0xffffffffu, idx, j + 3);
                        add_row(s0); add_row(s1); add_row(s2); add_row(s3);
                    }
                    for (; j < cnt; j++) add_row(__shfl_sync(0xffffffffu, idx, j));
                }
                const float si = g_sin[v];
                acc0 = fmaf(acc0, si, bvec_ok.x);
                acc1 = fmaf(acc1, si, bvec_ok.y);
                acc2 = fmaf(acc2, si, bvec_ok.z);
                acc3 = fmaf(acc3, si, bvec_ok.w);
            } else {
                acc0 = acc1 = acc2 = acc3 = 0.f;
            }
            uint2 hv;
            *(__half2*)&hv.x = __floats2half2_rn(acc0, acc1);
            *(__half2*)&hv.y = __floats2half2_rn(acc2, acc3);
            *(uint2*)(smem + HF_A_OFF + kch * HF_ACH + r * (GPAD * 2) + cc * 2) = hv;
        }
    }

    cp_wait_all();
    __syncthreads();

    // ---- phase 2: MMA (BM=128, BN=64, 4 k-chunks from SMEM) ----
    float c[4][2][4];
#pragma unroll
    for (int mi = 0; mi < 4; mi++)
#pragma unroll
        for (int ni = 0; ni < 2; ni++)
#pragma unroll
            for (int q = 0; q < 4; q++) c[mi][ni][q] = 0.f;

#pragma unroll
    for (int kt = 0; kt < 4; kt++) {
        const uint32_t sAh = sm + HF_A_OFF + (uint32_t)kt * HF_ACH;
        const uint32_t sBh = sm + HF_B_OFF + (uint32_t)kt * HF_BCH;
#pragma unroll
        for (int kk = 0; kk < 2; kk++) {
            const int kc = kk * 16;
            const int l16 = lane & 15;
            uint32_t bhf[2][2];
#pragma unroll
            for (int ni = 0; ni < 2; ni++) {
                const uint32_t boff =
                    (uint32_t)((wn * 16 + ni * 8 + (l16 & 7)) * GPAD + kc + (l16 >> 3) * 8) * 2u;
                ldsm_x2(bhf[ni], sBh + boff);
            }
#pragma unroll
            for (int mi = 0; mi < 4; mi++) {
                const uint32_t aoff =
                    (uint32_t)((wm * 64 + mi * 16 + (lane & 15)) * GPAD + kc + (lane >> 4) * 8) * 2u;
                uint32_t ahf[4];
                ldsm_x4(ahf, sAh + aoff);
#pragma unroll
                for (int ni = 0; ni < 2; ni++)
                    mma_fp16(c[mi][ni], ahf, bhf[ni]);
            }
        }
    }

    // ---- fused epilogue: relu(+bo1) dot Wo2, reduce to one float per row ----
    float* sred = (float*)(smem + HF_RED_OFF);    // [128][4]
    __syncthreads();
#pragma unroll
    for (int mi = 0; mi < 4; mi++) {
        float pA = 0.f, pB = 0.f;
#pragma unroll
        for (int ni = 0; ni < 2; ni++) {
            const int cl = wn * 16 + ni * 8 + 2 * (lane & 3);
            const float b0 = __ldg(bo1 + cl), b1 = __ldg(bo1 + cl + 1);
            const float w0 = __ldg(Wo2 + cl), w1 = __ldg(Wo2 + cl + 1);
            pA += fmaxf(c[mi][ni][0] + b0, 0.f) * w0 + fmaxf(c[mi][ni][1] + b1, 0.f) * w1;
            pB += fmaxf(c[mi][ni][2] + b0, 0.f) * w0 + fmaxf(c[mi][ni][3] + b1, 0.f) * w1;
        }
        pA += __shfl_xor_sync(0xffffffffu, pA, 1);
        pA += __shfl_xor_sync(0xffffffffu, pA, 2);
        pB += __shfl_xor_sync(0xffffffffu, pB, 1);
        pB += __shfl_xor_sync(0xffffffffu, pB, 2);
        if ((lane & 3) == 0) {
            const int wr = wm * 64 + mi * 16 + (lane >> 2);
            sred[wr * 4 + wn] = pA;
            sred[(wr + 8) * 4 + wn] = pB;
        }
    }
    __syncthreads();
    if (tid < 128) {
        const int row = bm * 128 + tid;
        if (row < M)
            out[row] = sred[tid * 4] + sred[tid * 4 + 1] + sred[tid * 4 + 2] +
                       sred[tid * 4 + 3] + __ldg(bo2);
    }
}

// ---------------- launch -----------------------------------------------------
extern "C" void kernel_launch(void* const* d_in, const int* in_sizes, int n_in,
                              void* d_out, int out_size) {
    const float* feat = (const float*)d_in[0];   // [N, 64, 8] -> [N, 512]
    const int*   src  = (const int*)d_in[1];
    const int*   dst  = (const int*)d_in[2];
    const float* W1   = (const float*)d_in[3];
    const float* b1   = (const float*)d_in[4];
    const float* W2   = (const float*)d_in[5];
    const float* b2   = (const float*)d_in[6];
    const float* Wo1  = (const float*)d_in[7];
    const float* bo1  = (const float*)d_in[8];
    const float* Wo2  = (const float*)d_in[9];
    const float* bo2  = (const float*)d_in[10];
    float* out = (float*)d_out;

    const int nb_nodes = (N_NODES + 255) / 256;
    const int mt64  = (N_NODES + 63) / 64;    // 1563
    const int mt128 = (N_NODES + 127) / 128;  // 782
    const int agrid = (N_NODES + 7) / 8;      // 12500

    __half *t1, *t2, *to1;
    cudaGetSymbolAddress((void**)&t1, g_W1t);
    cudaGetSymbolAddress((void**)&t2, g_W2t);
    cudaGetSymbolAddress((void**)&to1, g_Wo1t);

    cudaFuncSetAttribute(gemm1_wide,
                         cudaFuncAttributeMaxDynamicSharedMemorySize, G1_SMEM);
    cudaFuncSetAttribute(gemm2_fp16,
                         cudaFuncAttributeMaxDynamicSharedMemorySize, G2_SMEM);
    cudaFuncSetAttribute(head_fused,
                         cudaFuncAttributeMaxDynamicSharedMemorySize, HF_SMEM);

    // one-time side stream + fork/join events (reused across calls/capture)
    static cudaStream_t s_pre = nullptr;
    static cudaEvent_t ev_fork = nullptr, ev_scales = nullptr, ev_pre = nullptr;
    if (s_pre == nullptr) {
        cudaStreamCreateWithFlags(&s_pre, cudaStreamNonBlocking);
        cudaEventCreateWithFlags(&ev_fork, cudaEventDisableTiming);
        cudaEventCreateWithFlags(&ev_scales, cudaEventDisableTiming);
        cudaEventCreateWithFlags(&ev_pre, cudaEventDisableTiming);
    }

    // ---- fork: graph preprocessing on side stream ----
    // out-degree path first so GEMM1 (needs only sout) can start ASAP.
    cudaEventRecord(ev_fork, 0);
    cudaStreamWaitEvent(s_pre, ev_fork, 0);
    zero_deg_kernel<<<nb_nodes, 256, 0, s_pre>>>();
    degree_out_kernel<<<1024, 256, 0, s_pre>>>((const int4*)src);
    scales_out_kernel<<<nb_nodes, 256, 0, s_pre>>>();
    cudaEventRecord(ev_scales, s_pre);
    degree_in_kernel<<<1024, 256, 0, s_pre>>>((const int4*)dst);
    scales_in_kernel<<<nb_nodes, 256, 0, s_pre>>>();
    scan_block_kernel<<<SCAN_BLOCKS, 1024, 0, s_pre>>>();
    scan_part_kernel<<<1, 128, 0, s_pre>>>();
    scan_finish_kernel<<<nb_nodes, 256, 0, s_pre>>>();
    csr_fill_kernel<<<1024, 256, 0, s_pre>>>((const int4*)src, (const int4*)dst);
    cudaEventRecord(ev_pre, s_pre);

    // ---- main stream: weight transpose; GEMM1 waits only on sout ----
    wconv_kernel<<<(K1 * H1 + 255) / 256, 256>>>(W1, t1, K1, H1);
    wconv_kernel<<<(H1 * H2 + 255) / 256, 256>>>(W2, t2, H1, H2);
    wconv_kernel<<<(H2 * ENDD + 255) / 256, 256>>>(Wo1, to1, H2, ENDD);
    cudaStreamWaitEvent(0, ev_scales, 0);
    gemm1_wide<<<mt64, 256, G1_SMEM>>>(feat, t1, N_NODES);

    // ---- join: aggregation needs CSR + GEMM1 ----
    cudaStreamWaitEvent(0, ev_pre, 0);
    aggregate_warp1<<<agrid, 256>>>(b1);

    // layer 2 GEMM; head kernel fuses agg2 + MLP head
    gemm2_fp16<<<mt128, 256, G2_SMEM>>>(t2, N_NODES);
    head_fused<<<mt128, 256, HF_SMEM>>>(to1, b2, bo1, Wo2, bo2, out, N_NODES);
}

// round 16
// speedup vs baseline: 1.1915x; 1.1915x over previous
#include <cuda_runtime.h>
#include <cuda_bf16.h>
#include <cuda_fp16.h>
#include <cstdint>

#define N_NODES 100000
#define N_EDGES 3200000
#define K1 512      // in_dim * n_seq
#define H1 256
#define H2 128
#define ENDD 64

// ---------------- scratch (device globals; no allocation allowed) -----------
__device__ __half g_Hh[(size_t)N_NODES * H1];  // GEMM outputs, fp16 (agg input)
__device__ __half g_Xh[(size_t)N_NODES * H1];  // layer-2 GEMM input (agg1 out)
__device__ __half g_Xh2[(size_t)N_NODES * H2]; // head GEMM input (agg2 out)
__device__ int   g_deg_out[N_NODES];
__device__ int   g_deg_in[N_NODES];
__device__ float g_sout[N_NODES];
__device__ float g_sin[N_NODES];
__device__ int   g_rowptr[N_NODES + 1];
__device__ int   g_cursor[N_NODES];
__device__ int   g_colsrc[N_EDGES];
#define SCAN_BLOCKS ((N_NODES + 1023) / 1024)   // 98
__device__ int   g_part[128];
__device__ int   g_poff[128];
// transposed fp16 weights: Wt[n][k]
__device__ __half g_W1t[H1 * K1];
__device__ __half g_W2t[H2 * H1];
__device__ __half g_Wo1t[ENDD * H2];

// ---------------- PTX helpers ------------------------------------------------
__device__ __forceinline__ uint32_t smem_u32(const void* p) {
    uint32_t a;
    asm("{ .reg .u64 t; cvta.to.shared.u64 t, %1; cvt.u32.u64 %0, t; }"
        : "=r"(a) : "l"(p));
    return a;
}

__device__ __forceinline__ void ldsm_x4(uint32_t (&r)[4], uint32_t a) {
    asm volatile("ldmatrix.sync.aligned.m8n8.x4.shared.b16 {%0,%1,%2,%3}, [%4];"
                 : "=r"(r[0]), "=r"(r[1]), "=r"(r[2]), "=r"(r[3]) : "r"(a));
}

__device__ __forceinline__ void ldsm_x2(uint32_t (&r)[2], uint32_t a) {
    asm volatile("ldmatrix.sync.aligned.m8n8.x2.shared.b16 {%0,%1}, [%2];"
                 : "=r"(r[0]), "=r"(r[1]) : "r"(a));
}

__device__ __forceinline__ void mma_fp16(float (&d)[4], const uint32_t (&a)[4],
                                         const uint32_t (&b)[2]) {
    asm volatile(
        "mma.sync.aligned.m16n8k16.row.col.f32.f16.f16.f32 "
        "{%0,%1,%2,%3}, {%4,%5,%6,%7}, {%8,%9}, {%0,%1,%2,%3};"
        : "+f"(d[0]), "+f"(d[1]), "+f"(d[2]), "+f"(d[3])
        : "r"(a[0]), "r"(a[1]), "r"(a[2]), "r"(a[3]), "r"(b[0]), "r"(b[1]));
}

__device__ __forceinline__ void cp_async16(uint32_t smem_dst, const void* gsrc,
                                           int src_bytes) {
    asm volatile("cp.async.cg.shared.global [%0], [%1], 16, %2;"
                 :: "r"(smem_dst), "l"(gsrc), "r"(src_bytes));
}
__device__ __forceinline__ void cp_commit() {
    asm volatile("cp.async.commit_group;");
}
__device__ __forceinline__ void cp_wait_all() {
    asm volatile("cp.async.wait_group 0;");
}

// ---------------- graph preprocessing ---------------------------------------
__global__ void zero_deg_kernel() {
    int i = blockIdx.x * blockDim.x + threadIdx.x;
    if (i < N_NODES) { g_deg_out[i] = 0; g_deg_in[i] = 0; }
}

// split degree kernels (N_EDGES divisible by 4)
__global__ void degree_out_kernel(const int4* __restrict__ src4) {
    for (int i = blockIdx.x * blockDim.x + threadIdx.x; i < N_EDGES / 4;
         i += gridDim.x * blockDim.x) {
        int4 s = src4[i];
        atomicAdd(&g_deg_out[s.x], 1); atomicAdd(&g_deg_out[s.y], 1);
        atomicAdd(&g_deg_out[s.z], 1); atomicAdd(&g_deg_out[s.w], 1);
    }
}

__global__ void degree_in_kernel(const int4* __restrict__ dst4) {
    for (int i = blockIdx.x * blockDim.x + threadIdx.x; i < N_EDGES / 4;
         i += gridDim.x * blockDim.x) {
        int4 d = dst4[i];
        atomicAdd(&g_deg_in[d.x], 1); atomicAdd(&g_deg_in[d.y], 1);
        atomicAdd(&g_deg_in[d.z], 1); atomicAdd(&g_deg_in[d.w], 1);
    }
}

__global__ void scales_out_kernel() {
    int i = blockIdx.x * blockDim.x + threadIdx.x;
    if (i < N_NODES) g_sout[i] = rsqrtf((float)max(g_deg_out[i], 1));
}

__global__ void scales_in_kernel() {
    int i = blockIdx.x * blockDim.x + threadIdx.x;
    if (i < N_NODES) g_sin[i] = rsqrtf((float)max(g_deg_in[i], 1));
}

__global__ void scan_block_kernel() {
    __shared__ int sh[1024];
    int t = threadIdx.x;
    int i = blockIdx.x * 1024 + t;
    int v = (i < N_NODES) ? g_deg_in[i] : 0;
    sh[t] = v;
    __syncthreads();
    for (int off = 1; off < 1024; off <<= 1) {
        int x = sh[t];
        int y = (t >= off) ? sh[t - off] : 0;
        __syncthreads();
        sh[t] = x + y;
        __syncthreads();
    }
    if (i < N_NODES) g_rowptr[i] = sh[t] - v;
    if (t == 1023) g_part[blockIdx.x] = sh[1023];
}

__global__ void scan_part_kernel() {
    __shared__ int sh[128];
    int t = threadIdx.x;
    int v = (t < SCAN_BLOCKS) ? g_part[t] : 0;
    sh[t] = v;
    __syncthreads();
    for (int off = 1; off < 128; off <<= 1) {
        int x = sh[t];
        int y = (t >= off) ? sh[t - off] : 0;
        __syncthreads();
        sh[t] = x + y;
        __syncthreads();
    }
    g_poff[t] = sh[t] - v;
}

__global__ void scan_finish_kernel() {
    int i = blockIdx.x * blockDim.x + threadIdx.x;
    if (i < N_NODES) {
        int r = g_rowptr[i] + g_poff[i >> 10];
        g_rowptr[i] = r;
        g_cursor[i] = r;
    }
    if (i == 0) g_rowptr[N_NODES] = N_EDGES;
}

__global__ void csr_fill_kernel(const int4* __restrict__ src4,
                                const int4* __restrict__ dst4) {
    for (int i = blockIdx.x * blockDim.x + threadIdx.x; i < N_EDGES / 4;
         i += gridDim.x * blockDim.x) {
        int4 d = dst4[i];
        int4 s = src4[i];
        g_colsrc[atomicAdd(&g_cursor[d.x], 1)] = s.x;
        g_colsrc[atomicAdd(&g_cursor[d.y], 1)] = s.y;
        g_colsrc[atomicAdd(&g_cursor[d.z], 1)] = s.z;
        g_colsrc[atomicAdd(&g_cursor[d.w], 1)] = s.w;
    }
}

// ------- weight transpose to fp16: W[K][N] -> Wt[N][K] ----------------------
__global__ void wconv_kernel(const float* __restrict__ W, __half* __restrict__ T,
                             int K, int N) {
    int i = blockIdx.x * blockDim.x + threadIdx.x;
    if (i < K * N) {
        int k = i / N, n = i % N;
        T[(size_t)n * K + k] = __float2half_rn(W[i]);
    }
}

#define GPAD 40   // fp16 elements per SMEM row (80 B): conflict-free ldmatrix

// ---------------- GEMM1: fp32 A (feat), BM=64 x BN=256(all of N), BK=32 ------
// Epilogue multiplies row r by g_sout[r] (fp32, exact).
#define G1_AH_OFF   0u          // 64 x GPAD fp16 = 5120 (single)
#define G1_RAWA_OFF 5120u       // 2 x 8192 (64x32 fp32)
#define G1_RAWA_STR 8192u
#define G1_BH_OFF   21504u      // 2 x 20480 (256 x GPAD fp16)
#define G1_BSTAGE   20480u
#define G1_SMEM     62464

__global__ __launch_bounds__(256, 2)
void gemm1_wide(const float* __restrict__ A, const __half* __restrict__ Bh, int M) {
    extern __shared__ __align__(16) char smem[];
    const uint32_t sm = smem_u32(smem);

    const int tid = threadIdx.x;
    const int lane = tid & 31, warp = tid >> 5;
    const int wm = warp >> 2, wn = warp & 3;     // 2 x 4 warp grid
    const int bm = blockIdx.x;

    float c[2][8][4];
#pragma unroll
    for (int mi = 0; mi < 2; mi++)
#pragma unroll
        for (int ni = 0; ni < 8; ni++)
#pragma unroll
            for (int q = 0; q < 4; q++) c[mi][ni][q] = 0.f;

    const int kiters = K1 / 32;    // 16

    auto issue_stage = [&](int kt, int stage) {
        const int k0 = kt * 32;
        const uint32_t rawA = sm + G1_RAWA_OFF + (uint32_t)stage * G1_RAWA_STR;
#pragma unroll
        for (int j = 0; j < 2; j++) {
            const int cchunk = j * 256 + tid;             // 0..511
            const int row = cchunk >> 3, cc = (cchunk & 7) * 4;
            const int grow = bm * 64 + row;
            cp_async16(rawA + (uint32_t)(row * 128 + cc * 4),
                       A + (size_t)grow * K1 + k0 + cc, (grow < M) ? 16 : 0);
        }
        const uint32_t bh = sm + G1_BH_OFF + (uint32_t)stage * G1_BSTAGE;
#pragma unroll
        for (int j = 0; j < 4; j++) {
            const int cchunk = j * 256 + tid;             // 0..1023
            const int row = cchunk >> 2, cc = (cchunk & 3) * 8;   // row 0..255
            cp_async16(bh + (uint32_t)(row * (GPAD * 2) + cc * 2),
                       Bh + (size_t)row * K1 + k0 + cc, 16);
        }
        cp_commit();
    };

    issue_stage(0, 0);

    for (int kt = 0; kt < kiters; kt++) {
        const int stage = kt & 1;
        cp_wait_all();
        __syncthreads();

        if (kt + 1 < kiters) issue_stage(kt + 1, stage ^ 1);

        // convert rawA[stage] fp32 -> fp16 into single Ah buffer
        {
            const float4* raw =
                (const float4*)(smem + G1_RAWA_OFF + (uint32_t)stage * G1_RAWA_STR);
            __half* AhP = (__half*)(smem + G1_AH_OFF);
#pragma unroll
            for (int j = 0; j < 2; j++) {
                const int cchunk = j * 256 + tid;
                const int row = cchunk >> 3, col = (cchunk & 7) * 4;
                float4 v = raw[row * 8 + (cchunk & 7)];
                const int off = row * GPAD + col;
                *(__half2*)&AhP[off]     = __floats2half2_rn(v.x, v.y);
                *(__half2*)&AhP[off + 2] = __floats2half2_rn(v.z, v.w);
            }
        }
        __syncthreads();

        const uint32_t sAh = sm + G1_AH_OFF;
        const uint32_t sBh = sm + G1_BH_OFF + (uint32_t)stage * G1_BSTAGE;
#pragma unroll
        for (int kk = 0; kk < 2; kk++) {
            const int kc = kk * 16;
            const int l16 = lane & 15;
            uint32_t bhf[8][2];
#pragma unroll
            for (int ni = 0; ni < 8; ni++) {
                const uint32_t boff =
                    (uint32_t)((wn * 64 + ni * 8 + (l16 & 7)) * GPAD + kc + (l16 >> 3) * 8) * 2u;
                ldsm_x2(bhf[ni], sBh + boff);
            }
#pragma unroll
            for (int mi = 0; mi < 2; mi++) {
                const uint32_t aoff =
                    (uint32_t)((wm * 32 + mi * 16 + (lane & 15)) * GPAD + kc + (lane >> 4) * 8) * 2u;
                uint32_t ahf[4];
                ldsm_x4(ahf, sAh + aoff);
#pragma unroll
                for (int ni = 0; ni < 8; ni++)
                    mma_fp16(c[mi][ni], ahf, bhf[ni]);
            }
        }
    }

    // epilogue: row-scale by sout, then fp16 store
#pragma unroll
    for (int mi = 0; mi < 2; mi++) {
        const int r0 = bm * 64 + wm * 32 + mi * 16 + (lane >> 2);
        const float s0 = (r0 < M) ? g_sout[r0] : 0.f;
        const float s1 = (r0 + 8 < M) ? g_sout[r0 + 8] : 0.f;
#pragma unroll
        for (int ni = 0; ni < 8; ni++) {
            const int col = wn * 64 + ni * 8 + 2 * (lane & 3);
            if (r0 < M)
                *(__half2*)(g_Hh + (size_t)r0 * H1 + col) =
                    __floats2half2_rn(c[mi][ni][0] * s0, c[mi][ni][1] * s0);
            if (r0 + 8 < M)
                *(__half2*)(g_Hh + (size_t)(r0 + 8) * H1 + col) =
                    __floats2half2_rn(c[mi][ni][2] * s1, c[mi][ni][3] * s1);
        }
    }
}

// ---------------- GEMM2: fp16 A (g_Xh), BM=128 x BN=128, BK=32 ---------------
#define G2_AH_OFF  0u           // 2 x 10240
#define G2_AH_STR  10240u
#define G2_BH_OFF  20480u       // 2 x 10240
#define G2_BSTAGE  10240u
#define G2_SMEM    40960

__global__ __launch_bounds__(256, 2)
void gemm2_fp16(const __half* __restrict__ Bh, int M) {
    extern __shared__ __align__(16) char smem[];
    const uint32_t sm = smem_u32(smem);

    const int tid = threadIdx.x;
    const int lane = tid & 31, warp = tid >> 5;
    const int wm = warp >> 2, wn = warp & 3;
    const int bm = blockIdx.x;

    float c[4][4][4];
#pragma unroll
    for (int mi = 0; mi < 4; mi++)
#pragma unroll
        for (int ni = 0; ni < 4; ni++)
#pragma unroll
            for (int q = 0; q < 4; q++) c[mi][ni][q] = 0.f;

    const int kiters = H1 / 32;   // 8

    auto issue_stage = [&](int kt, int stage) {
        const int k0 = kt * 32;
        const uint32_t ah = sm + G2_AH_OFF + (uint32_t)stage * G2_AH_STR;
#pragma unroll
        for (int j = 0; j < 2; j++) {
            const int cchunk = j * 256 + tid;         // 0..511
            const int row = cchunk >> 2, cc = cchunk & 3;
            const int grow = bm * 128 + row;
            cp_async16(ah + (uint32_t)(row * (GPAD * 2) + cc * 16),
                       g_Xh + (size_t)grow * H1 + k0 + cc * 8,
                       (grow < M) ? 16 : 0);
        }
        const uint32_t bh = sm + G2_BH_OFF + (uint32_t)stage * G2_BSTAGE;
#pragma unroll
        for (int j = 0; j < 2; j++) {
            const int cchunk = j * 256 + tid;
            const int row = cchunk >> 2, cc = (cchunk & 3) * 8;
            cp_async16(bh + (uint32_t)(row * (GPAD * 2) + cc * 2),
                       Bh + (size_t)row * H1 + k0 + cc, 16);
        }
        cp_commit();
    };

    issue_stage(0, 0);

    for (int kt = 0; kt < kiters; kt++) {
        const int stage = kt & 1;
        cp_wait_all();
        __syncthreads();

        if (kt + 1 < kiters) issue_stage(kt + 1, stage ^ 1);

        const uint32_t sAh = sm + G2_AH_OFF + (uint32_t)stage * G2_AH_STR;
        const uint32_t sBh = sm + G2_BH_OFF + (uint32_t)stage * G2_BSTAGE;
#pragma unroll
        for (int kk = 0; kk < 2; kk++) {
            const int kc = kk * 16;
            const int l16 = lane & 15;
            uint32_t bhf[4][2];
#pragma unroll
            for (int ni = 0; ni < 4; ni++) {
                const uint32_t boff =
                    (uint32_t)((wn * 32 + ni * 8 + (l16 & 7)) * GPAD + kc + (l16 >> 3) * 8) * 2u;
                ldsm_x2(bhf[ni], sBh + boff);
            }
#pragma unroll
            for (int mi = 0; mi < 4; mi++) {
                const uint32_t aoff =
                    (uint32_t)((wm * 64 + mi * 16 + (lane & 15)) * GPAD + kc + (lane >> 4) * 8) * 2u;
                uint32_t ahf[4];
                ldsm_x4(ahf, sAh + aoff);
#pragma unroll
                for (int ni = 0; ni < 4; ni++)
                    mma_fp16(c[mi][ni], ahf, bhf[ni]);
            }
        }
    }

#pragma unroll
    for (int mi = 0; mi < 4; mi++) {
        const int r0 = bm * 128 + wm * 64 + mi * 16 + (lane >> 2);
#pragma unroll
        for (int ni = 0; ni < 4; ni++) {
            const int col = wn * 32 + ni * 8 + 2 * (lane & 3);
            if (r0 < M)
                *(__half2*)(g_Hh + (size_t)r0 * H2 + col) =
                    __floats2half2_rn(c[mi][ni][0], c[mi][ni][1]);
            if (r0 + 8 < M)
                *(__half2*)(g_Hh + (size_t)(r0 + 8) * H2 + col) =
                    __floats2half2_rn(c[mi][ni][2], c[mi][ni][3]);
        }
    }
}

// ---------------- head GEMM: out = relu(Xh2 @ Wo1 + bo1) @ Wo2 + bo2 ---------
#define HG_AH_OFF  0u           // 2 x 10240
#define HG_AH_STR  10240u
#define HG_BH_OFF  20480u       // 2 x 5120 (64 x GPAD)
#define HG_BSTAGE  5120u
#define HG_RED_OFF 30720u       // 128 x 4 floats
#define HG_SMEM    32768

__global__ __launch_bounds__(256, 2)
void head_gemm(const __half* __restrict__ Bh, const float* __restrict__ bo1,
               const float* __restrict__ Wo2, const float* __restrict__ bo2,
               float* __restrict__ out, int M) {
    extern __shared__ __align__(16) char smem[];
    const uint32_t sm = smem_u32(smem);

    const int tid = threadIdx.x;
    const int lane = tid & 31, warp = tid >> 5;
    const int wm = warp >> 2, wn = warp & 3;
    const int bm = blockIdx.x;

    float c[4][2][4];
#pragma unroll
    for (int mi = 0; mi < 4; mi++)
#pragma unroll
        for (int ni = 0; ni < 2; ni++)
#pragma unroll
            for (int q = 0; q < 4; q++) c[mi][ni][q] = 0.f;

    const int kiters = H2 / 32;   // 4

    auto issue_stage = [&](int kt, int stage) {
        const int k0 = kt * 32;
        const uint32_t ah = sm + HG_AH_OFF + (uint32_t)stage * HG_AH_STR;
#pragma unroll
        for (int j = 0; j < 2; j++) {
            const int cchunk = j * 256 + tid;         // 0..511
            const int row = cchunk >> 2, cc = cchunk & 3;
            const int grow = bm * 128 + row;
            cp_async16(ah + (uint32_t)(row * (GPAD * 2) + cc * 16),
                       g_Xh2 + (size_t)grow * H2 + k0 + cc * 8,
                       (grow < M) ? 16 : 0);
        }
        const uint32_t bh = sm + HG_BH_OFF + (uint32_t)stage * HG_BSTAGE;
        if (tid < 256) {                              // 64 rows x 4 chunks
            const int row = tid >> 2, cc = (tid & 3) * 8;
            cp_async16(bh + (uint32_t)(row * (GPAD * 2) + cc * 2),
                       Bh + (size_t)row * H2 + k0 + cc, 16);
        }
        cp_commit();
    };

    issue_stage(0, 0);

    for (int kt = 0; kt < kiters; kt++) {
        const int stage = kt & 1;
        cp_wait_all();
        __syncthreads();

        if (kt + 1 < kiters) issue_stage(kt + 1, stage ^ 1);

        const uint32_t sAh = sm + HG_AH_OFF + (uint32_t)stage * HG_AH_STR;
        const uint32_t sBh = sm + HG_BH_OFF + (uint32_t)stage * HG_BSTAGE;
#pragma unroll
        for (int kk = 0; kk < 2; kk++) {
            const int kc = kk * 16;
            const int l16 = lane & 15;
            uint32_t bhf[2][2];
#pragma unroll
            for (int ni = 0; ni < 2; ni++) {
                const uint32_t boff =
                    (uint32_t)((wn * 16 + ni * 8 + (l16 & 7)) * GPAD + kc + (l16 >> 3) * 8) * 2u;
                ldsm_x2(bhf[ni], sBh + boff);
            }
#pragma unroll
            for (int mi = 0; mi < 4; mi++) {
                const uint32_t aoff =
                    (uint32_t)((wm * 64 + mi * 16 + (lane & 15)) * GPAD + kc + (lane >> 4) * 8) * 2u;
                uint32_t ahf[4];
                ldsm_x4(ahf, sAh + aoff);
#pragma unroll
                for (int ni = 0; ni < 2; ni++)
                    mma_fp16(c[mi][ni], ahf, bhf[ni]);
            }
        }
    }

    // ---- fused epilogue: relu(+bo1) dot Wo2, reduce to one float per row ----
    float* sred = (float*)(smem + HG_RED_OFF);    // [128][4]
    __syncthreads();
#pragma unroll
    for (int mi = 0; mi < 4; mi++) {
        float pA = 0.f, pB = 0.f;
#pragma unroll
        for (int ni = 0; ni < 2; ni++) {
            const int cl = wn * 16 + ni * 8 + 2 * (lane & 3);
            const float b0 = __ldg(bo1 + cl), b1 = __ldg(bo1 + cl + 1);
            const float w0 = __ldg(Wo2 + cl), w1 = __ldg(Wo2 + cl + 1);
            pA += fmaxf(c[mi][ni][0] + b0, 0.f) * w0 + fmaxf(c[mi][ni][1] + b1, 0.f) * w1;
            pB += fmaxf(c[mi][ni][2] + b0, 0.f) * w0 + fmaxf(c[mi][ni][3] + b1, 0.f) * w1;
        }
        pA += __shfl_xor_sync(0xffffffffu, pA, 1);
        pA += __shfl_xor_sync(0xffffffffu, pA, 2);
        pB += __shfl_xor_sync(0xffffffffu, pB, 1);
        pB += __shfl_xor_sync(0xffffffffu, pB, 2);
        if ((lane & 3) == 0) {
            const int wr = wm * 64 + mi * 16 + (lane >> 2);
            sred[wr * 4 + wn] = pA;
            sred[(wr + 8) * 4 + wn] = pB;
        }
    }
    __syncthreads();
    if (tid < 128) {
        const int row = bm * 128 + tid;
        if (row < M)
            out[row] = sred[tid * 4] + sred[tid * 4 + 1] + sred[tid * 4 + 2] +
                       sred[tid * 4 + 3] + __ldg(bo2);
    }
}

// ---------------- warp-per-node aggregation (fp16 gather, LDG.128) ----------
// One warp per node; shfl-distributed index prefetch; one LDG.128 per edge.
// H rows pre-scaled by sout (GEMM1 epilogue) for layer 1.
template <int COLS, bool L1MODE>
__global__ __launch_bounds__(256)
void aggregate_warp(const float* __restrict__ bias) {
    const int warp = threadIdx.x >> 5, lane = threadIdx.x & 31;
    const int v = blockIdx.x * 8 + warp;
    if (v >= N_NODES) return;
    constexpr int EPT = COLS / 32;        // 8 (agg1) or 4 (agg2)

    float acc[EPT];
#pragma unroll
    for (int i = 0; i < EPT; i++) acc[i] = 0.f;

    const __half* __restrict__ Hm = g_Hh;

    auto add_row = [&](int s) {
        const __half* r = Hm + (size_t)s * COLS + lane * EPT;
        if constexpr (EPT == 8) {
            const uint4 d = *(const uint4*)r;
            const float2 f0 = __half22float2(*(const __half2*)&d.x);
            const float2 f1 = __half22float2(*(const __half2*)&d.y);
            const float2 f2 = __half22float2(*(const __half2*)&d.z);
            const float2 f3 = __half22float2(*(const __half2*)&d.w);
            acc[0] += f0.x; acc[1] += f0.y; acc[2] += f1.x; acc[3] += f1.y;
            acc[4] += f2.x; acc[5] += f2.y; acc[6] += f3.x; acc[7] += f3.y;
        } else {
            const uint2 d = *(const uint2*)r;
            const float2 f0 = __half22float2(*(const __half2*)&d.x);
            const float2 f1 = __half22float2(*(const __half2*)&d.y);
            acc[0] += f0.x; acc[1] += f0.y; acc[2] += f1.x; acc[3] += f1.y;
        }
    };

    const int beg = g_rowptr[v];
    const int end = g_rowptr[v + 1];
    for (int base = beg; base < end; base += 32) {
        const int cnt = min(32, end - base);
        int idx = 0;
        if (lane < cnt) idx = g_colsrc[base + lane];
        int j = 0;
        for (; j + 4 <= cnt; j += 4) {
            const int s0 = __shfl_sync(0xffffffffu, idx, j);
            const int s1 = __shfl_sync(0xffffffffu, idx, j + 1);
            const int s2 = __shfl_sync(0xffffffffu, idx, j + 2);
            const int s3 = __shfl_sync(0xffffffffu, idx, j + 3);
            add_row(s0); add_row(s1); add_row(s2); add_row(s3);
        }
        for (; j < cnt; j++) add_row(__shfl_sync(0xffffffffu, idx, j));
    }

    const float si = g_sin[v];
    float o[EPT];
#pragma unroll
    for (int i = 0; i < EPT; i += 4) {
        const float4 b = *(const float4*)(bias + lane * EPT + i);
        o[i]     = fmaf(acc[i],     si, b.x);
        o[i + 1] = fmaf(acc[i + 1], si, b.y);
        o[i + 2] = fmaf(acc[i + 2], si, b.z);
        o[i + 3] = fmaf(acc[i + 3], si, b.w);
    }

    __half2 h[EPT / 2];
    if constexpr (L1MODE) {
        const float so = g_sout[v];
#pragma unroll
        for (int i = 0; i < EPT; i++) o[i] = fmaxf(o[i], 0.f) * so;
#pragma unroll
        for (int i = 0; i < EPT / 2; i++) h[i] = __floats2half2_rn(o[2 * i], o[2 * i + 1]);
        if constexpr (EPT == 8)
            *(uint4*)(g_Xh + (size_t)v * COLS + lane * EPT) = *(uint4*)h;
        else
            *(uint2*)(g_Xh + (size_t)v * COLS + lane * EPT) = *(uint2*)h;
    } else {
#pragma unroll
        for (int i = 0; i < EPT / 2; i++) h[i] = __floats2half2_rn(o[2 * i], o[2 * i + 1]);
        if constexpr (EPT == 8)
            *(uint4*)(g_Xh2 + (size_t)v * COLS + lane * EPT) = *(uint4*)h;
        else
            *(uint2*)(g_Xh2 + (size_t)v * COLS + lane * EPT) = *(uint2*)h;
    }
}

// ---------------- launch -----------------------------------------------------
extern "C" void kernel_launch(void* const* d_in, const int* in_sizes, int n_in,
                              void* d_out, int out_size) {
    const float* feat = (const float*)d_in[0];   // [N, 64, 8] -> [N, 512]
    const int*   src  = (const int*)d_in[1];
    const int*   dst  = (const int*)d_in[2];
    const float* W1   = (const float*)d_in[3];
    const float* b1   = (const float*)d_in[4];
    const float* W2   = (const float*)d_in[5];
    const float* b2   = (const float*)d_in[6];
    const float* Wo1  = (const float*)d_in[7];
    const float* bo1  = (const float*)d_in[8];
    const float* Wo2  = (const float*)d_in[9];
    const float* bo2  = (const float*)d_in[10];
    float* out = (float*)d_out;

    const int nb_nodes = (N_NODES + 255) / 256;
    const int mt64  = (N_NODES + 63) / 64;    // 1563
    const int mt128 = (N_NODES + 127) / 128;  // 782
    const int agrid = (N_NODES + 7) / 8;      // 12500

    __half *t1, *t2, *to1;
    cudaGetSymbolAddress((void**)&t1, g_W1t);
    cudaGetSymbolAddress((void**)&t2, g_W2t);
    cudaGetSymbolAddress((void**)&to1, g_Wo1t);

    cudaFuncSetAttribute(gemm1_wide,
                         cudaFuncAttributeMaxDynamicSharedMemorySize, G1_SMEM);
    cudaFuncSetAttribute(gemm2_fp16,
                         cudaFuncAttributeMaxDynamicSharedMemorySize, G2_SMEM);
    cudaFuncSetAttribute(head_gemm,
                         cudaFuncAttributeMaxDynamicSharedMemorySize, HG_SMEM);

    // one-time side stream + fork/join events (reused across calls/capture)
    static cudaStream_t s_pre = nullptr;
    static cudaEvent_t ev_fork = nullptr, ev_scales = nullptr, ev_pre = nullptr;
    if (s_pre == nullptr) {
        cudaStreamCreateWithFlags(&s_pre, cudaStreamNonBlocking);
        cudaEventCreateWithFlags(&ev_fork, cudaEventDisableTiming);
        cudaEventCreateWithFlags(&ev_scales, cudaEventDisableTiming);
        cudaEventCreateWithFlags(&ev_pre, cudaEventDisableTiming);
    }

    // ---- fork: graph preprocessing on side stream ----
    // out-degree path first so GEMM1 (needs only sout) can start ASAP.
    cudaEventRecord(ev_fork, 0);
    cudaStreamWaitEvent(s_pre, ev_fork, 0);
    zero_deg_kernel<<<nb_nodes, 256, 0, s_pre>>>();
    degree_out_kernel<<<1024, 256, 0, s_pre>>>((const int4*)src);
    scales_out_kernel<<<nb_nodes, 256, 0, s_pre>>>();
    cudaEventRecord(ev_scales, s_pre);
    degree_in_kernel<<<1024, 256, 0, s_pre>>>((const int4*)dst);
    scales_in_kernel<<<nb_nodes, 256, 0, s_pre>>>();
    scan_block_kernel<<<SCAN_BLOCKS, 1024, 0, s_pre>>>();
    scan_part_kernel<<<1, 128, 0, s_pre>>>();
    scan_finish_kernel<<<nb_nodes, 256, 0, s_pre>>>();
    csr_fill_kernel<<<1024, 256, 0, s_pre>>>((const int4*)src, (const int4*)dst);
    cudaEventRecord(ev_pre, s_pre);

    // ---- main stream: weight transpose; GEMM1 waits only on sout ----
    wconv_kernel<<<(K1 * H1 + 255) / 256, 256>>>(W1, t1, K1, H1);
    wconv_kernel<<<(H1 * H2 + 255) / 256, 256>>>(W2, t2, H1, H2);
    wconv_kernel<<<(H2 * ENDD + 255) / 256, 256>>>(Wo1, to1, H2, ENDD);
    cudaStreamWaitEvent(0, ev_scales, 0);
    gemm1_wide<<<mt64, 256, G1_SMEM>>>(feat, t1, N_NODES);

    // ---- join: aggregation needs CSR + GEMM1 ----
    cudaStreamWaitEvent(0, ev_pre, 0);
    aggregate_warp<H1, true><<<agrid, 256>>>(b1);

    // layer 2 (fp16 A directly from g_Xh; agg2 -> fp16 g_Xh2)
    gemm2_fp16<<<mt128, 256, G2_SMEM>>>(t2, N_NODES);
    aggregate_warp<H2, false><<<agrid, 256>>>(b2);

    // fused head GEMM (relu + Wo2 dot in epilogue)
    head_gemm<<<mt128, 256, HG_SMEM>>>(to1, bo1, Wo2, bo2, out, N_NODES);
}